// round 7
// baseline (speedup 1.0000x reference)
#include <cuda_runtime.h>
#include <cuda_fp16.h>
#include <cstdint>
#include <math.h>

#define NTOK 16384
#define DM   1024
#define DFFN 4096
#define NE   8
#define TOPK 2
#define NSLOT (NTOK * TOPK)

#define BM 128
#define BN 256
#define BK 32
#define STAGES 4
#define THREADS 256
#define GRID_PERSIST 148

// ---------------- device scratch (static globals: allocation-free) ----------
__device__ int   g_cnt[NE];
__device__ int   g_tok[NE * NTOK];
__device__ float g_wt [NE * NTOK];
__device__ int   g_work1, g_work2;

// padded by BM rows so tile-overhang reads stay in bounds (never written -> 0)
__device__ __align__(16) __half XGH[(size_t)(NSLOT + BM) * DM];
__device__ __align__(16) __half HH [(size_t)(NSLOT + BM) * DFFN];
__device__ __align__(16) __half W1H[(size_t)NE * DM * DFFN];
__device__ __align__(16) __half W1L[(size_t)NE * DM * DFFN];
__device__ __align__(16) __half W2H[(size_t)NE * DFFN * DM];
__device__ __align__(16) __half W2L[(size_t)NE * DFFN * DM];

// ---------------- asm helpers ----------------------------------------------
__device__ __forceinline__ void cp16(uint32_t dst, const void* src) {
    asm volatile("cp.async.cg.shared.global [%0], [%1], 16;" :: "r"(dst), "l"(src));
}
#define CP_COMMIT() asm volatile("cp.async.commit_group;" ::: "memory")
#define CP_WAIT(n)  asm volatile("cp.async.wait_group %0;" :: "n"(n) : "memory")

#define LDSM_X4(r0, r1, r2, r3, addr) \
    asm volatile("ldmatrix.sync.aligned.m8n8.x4.shared.b16 {%0,%1,%2,%3}, [%4];" \
                 : "=r"(r0), "=r"(r1), "=r"(r2), "=r"(r3) : "r"(addr))
#define LDSM_X4T(r0, r1, r2, r3, addr) \
    asm volatile("ldmatrix.sync.aligned.m8n8.x4.trans.shared.b16 {%0,%1,%2,%3}, [%4];" \
                 : "=r"(r0), "=r"(r1), "=r"(r2), "=r"(r3) : "r"(addr))

__device__ __forceinline__ void mma_f16(float* c, const uint32_t* a,
                                        uint32_t b0, uint32_t b1) {
    asm volatile(
        "mma.sync.aligned.m16n8k16.row.col.f32.f16.f16.f32 "
        "{%0,%1,%2,%3}, {%4,%5,%6,%7}, {%8,%9}, {%0,%1,%2,%3};"
        : "+f"(c[0]), "+f"(c[1]), "+f"(c[2]), "+f"(c[3])
        : "r"(a[0]), "r"(a[1]), "r"(a[2]), "r"(a[3]), "r"(b0), "r"(b1));
}

// ---------------- smem layout: per stage 40KB ------------------------------
// A 128x32 fp16 (8KB), Bh 32x256 (16KB), Bl (16KB)
#define STAGE_BYTES 40960u
#define SA(s)   ((uint32_t)(s) * STAGE_BYTES)
#define SB_H(s) ((uint32_t)(s) * STAGE_BYTES + 8192u)
#define SB_L(s) ((uint32_t)(s) * STAGE_BYTES + 24576u)
#define SMEM_SZ (STAGES * 40960)

// A: row pitch 64B (4x16B chunks), swizzle chunk ^= (row>>1)&3 (conflict-free)
__device__ __forceinline__ uint32_t a_off(int row, int ch) {
    return (uint32_t)(row * 64 + ((ch ^ ((row >> 1) & 3)) << 4));
}
// B: row pitch 512B (32x16B chunks), swizzle low3 of chunk ^= k&7
__device__ __forceinline__ uint32_t b_off(int k, int ch) {
    return (uint32_t)(k * 512 + (((ch & ~7) | ((ch ^ k) & 7)) << 4));
}

__device__ __forceinline__ float gelu_f(float v) {
    return 0.5f * v * (1.f + erff(v * 0.70710678118654752440f));
}
__device__ __forceinline__ uint32_t pack_h2(float a, float b) {
    __half x = __float2half_rn(a), y = __float2half_rn(b);
    return (uint32_t)__half_as_ushort(x) | ((uint32_t)__half_as_ushort(y) << 16);
}
__device__ __forceinline__ int expert_off(int e) {
    int off = 0;
#pragma unroll
    for (int i = 0; i < NE; i++) if (i < e) off += g_cnt[i];
    return off;
}
// map linear work item -> (expert, row block, col block); false when done
__device__ __forceinline__ bool map_item(int item, int nx, int& e, int& yb, int& xb) {
    int rem = item;
#pragma unroll
    for (int i = 0; i < NE; i++) {
        int nyb = (g_cnt[i] + BM - 1) / BM;
        int ne = nyb * nx;
        if (rem < ne) { e = i; yb = rem / nx; xb = rem - yb * nx; return true; }
        rem -= ne;
    }
    return false;
}

// ---------------- stage loader ----------------------------------------------
__device__ __forceinline__ void load_stage(
    uint32_t sb, int stage, const __half* __restrict__ A, size_t lda,
    const __half* __restrict__ Bh, const __half* __restrict__ Bl, size_t ldb,
    size_t arow0, int k0, int n0, int tid) {
#pragma unroll
    for (int i = 0; i < 2; i++) {           // A: 512 chunks
        int ca = tid + 256 * i;
        int row = ca >> 2, ch = ca & 3;
        size_t gsrc = (arow0 + row) * lda + k0 + ch * 8;
        cp16(sb + SA(stage) + a_off(row, ch), A + gsrc);
    }
#pragma unroll
    for (int i = 0; i < 4; i++) {           // B: 1024 chunks per buffer
        int cb = tid + 256 * i;
        int k = cb >> 5, ch = cb & 31;
        uint32_t off = b_off(k, ch);
        size_t gsrc = (size_t)(k0 + k) * ldb + n0 + ch * 8;
        cp16(sb + SB_H(stage) + off, Bh + gsrc);
        cp16(sb + SB_L(stage) + off, Bl + gsrc);
    }
}

// ---------------- per-stage compute: 2-pass fp16 split (R5 structure) -------
// warp grid 2x4, warp tile 64x64, acc[4][8][4]
__device__ __forceinline__ void compute_stage(
    uint32_t sb, int stage, float acc[4][8][4], int wm, int wn, int lane) {
    uint32_t sa = sb + SA(stage);
    uint32_t sbH = sb + SB_H(stage), sbL = sb + SB_L(stage);
    int l15 = lane & 15, l16 = lane >> 4;
#pragma unroll
    for (int half = 0; half < 2; half++) {     // kk = half*16
        uint32_t ah[4][4];
#pragma unroll
        for (int mt = 0; mt < 4; mt++) {
            int row = wm * 64 + mt * 16 + l15;
            LDSM_X4(ah[mt][0], ah[mt][1], ah[mt][2], ah[mt][3],
                    sa + a_off(row, half * 2 + l16));
        }
        uint32_t bf[8][2];
        int kk = half * 16 + l15;
#pragma unroll
        for (int ng = 0; ng < 4; ng++) {
            uint32_t off = b_off(kk, wn * 8 + ng * 2 + l16);
            LDSM_X4T(bf[2 * ng][0], bf[2 * ng][1],
                     bf[2 * ng + 1][0], bf[2 * ng + 1][1], sbH + off);
        }
#pragma unroll
        for (int mt = 0; mt < 4; mt++)
#pragma unroll
            for (int nt = 0; nt < 8; nt++)
                mma_f16(acc[mt][nt], ah[mt], bf[nt][0], bf[nt][1]);
#pragma unroll
        for (int ng = 0; ng < 4; ng++) {
            uint32_t off = b_off(kk, wn * 8 + ng * 2 + l16);
            LDSM_X4T(bf[2 * ng][0], bf[2 * ng][1],
                     bf[2 * ng + 1][0], bf[2 * ng + 1][1], sbL + off);
        }
#pragma unroll
        for (int mt = 0; mt < 4; mt++)
#pragma unroll
            for (int nt = 0; nt < 8; nt++)
                mma_f16(acc[mt][nt], ah[mt], bf[nt][0], bf[nt][1]);
    }
}

// ---------------- launch 0: zero output + counters ---------------------------
__global__ void zero_kernel(float* __restrict__ out) {
    size_t i = (size_t)blockIdx.x * blockDim.x + threadIdx.x;
    const size_t tot4 = (size_t)NTOK * DM / 4;
    if (i < tot4) ((float4*)out)[i] = make_float4(0.f, 0.f, 0.f, 0.f);
    if (i < NE) g_cnt[i] = 0;
    if (i == 0) { g_work1 = 0; g_work2 = 0; }
}

// ---------------- launch 1: gating (one warp / token) ------------------------
__global__ __launch_bounds__(256) void gating_kernel(
    const float* __restrict__ x, const float* __restrict__ gW,
    const float* __restrict__ gb, float* __restrict__ out_topi, int write_topi) {
    int warp = (int)((blockIdx.x * blockDim.x + threadIdx.x) >> 5);
    int lane = threadIdx.x & 31;
    if (warp >= NTOK) return;
    const float* xr = x + (size_t)warp * DM;
    float acc[NE];
#pragma unroll
    for (int e = 0; e < NE; e++) acc[e] = 0.f;
    for (int d = lane; d < DM; d += 32) {
        float xv = xr[d];
        const float4* w4 = (const float4*)(gW + d * NE);
        float4 wa = w4[0], wb = w4[1];
        acc[0] += xv * wa.x; acc[1] += xv * wa.y;
        acc[2] += xv * wa.z; acc[3] += xv * wa.w;
        acc[4] += xv * wb.x; acc[5] += xv * wb.y;
        acc[6] += xv * wb.z; acc[7] += xv * wb.w;
    }
#pragma unroll
    for (int e = 0; e < NE; e++)
#pragma unroll
        for (int o = 16; o > 0; o >>= 1)
            acc[e] += __shfl_xor_sync(0xffffffffu, acc[e], o);
    if (lane == 0) {
        float v0 = -1e30f, v1 = -1e30f; int i0 = 0, i1 = 0;
#pragma unroll
        for (int e = 0; e < NE; e++) {
            float l = acc[e] + gb[e];
            if (l > v0)      { v1 = v0; i1 = i0; v0 = l; i0 = e; }
            else if (l > v1) { v1 = l;  i1 = e; }
        }
        float e1 = expf(v1 - v0);
        float s  = 1.f + e1;
        float w0 = 1.f / s, w1 = e1 / s;
        int p0 = atomicAdd(&g_cnt[i0], 1);
        g_tok[i0 * NTOK + p0] = warp; g_wt[i0 * NTOK + p0] = w0;
        int p1 = atomicAdd(&g_cnt[i1], 1);
        g_tok[i1 * NTOK + p1] = warp; g_wt[i1 * NTOK + p1] = w1;
        if (write_topi) {
            out_topi[warp * 2 + 0] = (float)i0;
            out_topi[warp * 2 + 1] = (float)i1;
        }
    }
}

// ---------------- launch 2: fused prep (weight splits + routed gather) -------
__global__ __launch_bounds__(256) void prep_kernel(
    const float* __restrict__ x, const float* __restrict__ W1,
    const float* __restrict__ W2) {
    const size_t n4 = (size_t)NE * DM * DFFN / 4;
    if (blockIdx.y < 2) {                       // weight hi/lo split (fp16)
        size_t i = (size_t)blockIdx.x * blockDim.x + threadIdx.x;
        if (i >= n4) return;
        const float* src = blockIdx.y ? W2 : W1;
        __half* dh = blockIdx.y ? W2H : W1H;
        __half* dl = blockIdx.y ? W2L : W1L;
        float4 v = ((const float4*)src)[i];
        __half a0 = __float2half_rn(v.x), a1 = __float2half_rn(v.y);
        __half a2 = __float2half_rn(v.z), a3 = __float2half_rn(v.w);
        uint2 hh, ll;
        hh.x = (uint32_t)__half_as_ushort(a0) | ((uint32_t)__half_as_ushort(a1) << 16);
        hh.y = (uint32_t)__half_as_ushort(a2) | ((uint32_t)__half_as_ushort(a3) << 16);
        ll.x = pack_h2(v.x - __half2float(a0), v.y - __half2float(a1));
        ll.y = pack_h2(v.z - __half2float(a2), v.w - __half2float(a3));
        ((uint2*)dh)[i] = hh;
        ((uint2*)dl)[i] = ll;
    } else {                                    // gather routed rows -> fp16
        int e = blockIdx.x >> 12;               // 4096 x-blocks per expert
        int cnt = g_cnt[e], off = expert_off(e);
        int rbase = (blockIdx.x & 4095) * 4;
#pragma unroll
        for (int rr = 0; rr < 4; rr++) {
            int r = rbase + rr;
            if (r >= cnt) continue;
            int tok = g_tok[e * NTOK + r];
            float4 v = ((const float4*)(x + (size_t)tok * DM))[threadIdx.x];
            uint2 hh;
            hh.x = pack_h2(v.x, v.y); hh.y = pack_h2(v.z, v.w);
            ((uint2*)(XGH + (size_t)(off + r) * DM))[threadIdx.x] = hh;
        }
    }
}

// ---------------- launch 3: GEMM1 (persistent, R5 mainloop) ------------------
__global__ __launch_bounds__(THREADS, 1) void gemm1_mma(const float* __restrict__ b1) {
    extern __shared__ char smem[];
    __shared__ int s_item;
    uint32_t sb = (uint32_t)__cvta_generic_to_shared(smem);
    int tid = threadIdx.x, lane = tid & 31, wid = tid >> 5;
    int wm = wid & 1, wn = wid >> 1;
    const int NX = DFFN / BN;                   // 16
    const int nk = DM / BK;                     // 32

    for (;;) {
        if (tid == 0) s_item = atomicAdd(&g_work1, 1);
        __syncthreads();
        int e, yb, xb;
        if (!map_item(s_item, NX, e, yb, xb)) break;
        int rows = g_cnt[e], off = expert_off(e);
        int row0 = yb * BM, n0 = xb * BN;
        const __half* Bh = W1H + (size_t)e * DM * DFFN;
        const __half* Bl = W1L + (size_t)e * DM * DFFN;
        size_t arow0 = (size_t)off + row0;

        float acc[4][8][4];
#pragma unroll
        for (int a = 0; a < 4; a++)
#pragma unroll
            for (int b = 0; b < 8; b++)
#pragma unroll
                for (int c = 0; c < 4; c++) acc[a][b][c] = 0.f;

#pragma unroll
        for (int p = 0; p < STAGES - 1; p++) {
            load_stage(sb, p, XGH, DM, Bh, Bl, DFFN, arow0, p * BK, n0, tid);
            CP_COMMIT();
        }
        for (int t = 0; t < nk; t++) {
            CP_WAIT(STAGES - 2);
            __syncthreads();
            int nx = t + STAGES - 1;
            if (nx < nk)
                load_stage(sb, nx % STAGES, XGH, DM, Bh, Bl, DFFN,
                           arow0, nx * BK, n0, tid);
            CP_COMMIT();
            compute_stage(sb, t % STAGES, acc, wm, wn, lane);
        }
        CP_WAIT(0);

        const float* bias = b1 + (size_t)e * DFFN;
        int quad = lane >> 2, pair = lane & 3;
#pragma unroll
        for (int mt = 0; mt < 4; mt++) {
            int rb = row0 + wm * 64 + mt * 16 + quad;
#pragma unroll
            for (int nt = 0; nt < 8; nt++) {
                int col = n0 + wn * 64 + nt * 8 + pair * 2;
                float bs0 = __ldg(&bias[col]), bs1 = __ldg(&bias[col + 1]);
                if (rb < rows) {
                    size_t o = (size_t)(off + rb) * DFFN + col;
                    *(uint32_t*)(HH + o) = pack_h2(gelu_f(acc[mt][nt][0] + bs0),
                                                   gelu_f(acc[mt][nt][1] + bs1));
                }
                if (rb + 8 < rows) {
                    size_t o = (size_t)(off + rb + 8) * DFFN + col;
                    *(uint32_t*)(HH + o) = pack_h2(gelu_f(acc[mt][nt][2] + bs0),
                                                   gelu_f(acc[mt][nt][3] + bs1));
                }
            }
        }
        __syncthreads();
    }
}

// ---------------- launch 4: GEMM2 (persistent, R5 mainloop) ------------------
__global__ __launch_bounds__(THREADS, 1) void gemm2_mma(
    const float* __restrict__ b2, float* __restrict__ out) {
    extern __shared__ char smem[];
    __shared__ int s_item;
    uint32_t sb = (uint32_t)__cvta_generic_to_shared(smem);
    int tid = threadIdx.x, lane = tid & 31, wid = tid >> 5;
    int wm = wid & 1, wn = wid >> 1;
    const int NX = DM / BN;                     // 4
    const int nk = DFFN / BK;                   // 128

    for (;;) {
        if (tid == 0) s_item = atomicAdd(&g_work2, 1);
        __syncthreads();
        int e, yb, xb;
        if (!map_item(s_item, NX, e, yb, xb)) break;
        int rows = g_cnt[e], off = expert_off(e);
        int row0 = yb * BM, n0 = xb * BN;
        const __half* Bh = W2H + (size_t)e * DFFN * DM;
        const __half* Bl = W2L + (size_t)e * DFFN * DM;
        size_t arow0 = (size_t)off + row0;

        float acc[4][8][4];
#pragma unroll
        for (int a = 0; a < 4; a++)
#pragma unroll
            for (int b = 0; b < 8; b++)
#pragma unroll
                for (int c = 0; c < 4; c++) acc[a][b][c] = 0.f;

#pragma unroll
        for (int p = 0; p < STAGES - 1; p++) {
            load_stage(sb, p, HH, DFFN, Bh, Bl, DM, arow0, p * BK, n0, tid);
            CP_COMMIT();
        }
        for (int t = 0; t < nk; t++) {
            CP_WAIT(STAGES - 2);
            __syncthreads();
            int nx = t + STAGES - 1;
            if (nx < nk)
                load_stage(sb, nx % STAGES, HH, DFFN, Bh, Bl, DM,
                           arow0, nx * BK, n0, tid);
            CP_COMMIT();
            compute_stage(sb, t % STAGES, acc, wm, wn, lane);
        }
        CP_WAIT(0);

        const float* bias = b2 + (size_t)e * DM;
        int quad = lane >> 2, pair = lane & 3;
#pragma unroll
        for (int mt = 0; mt < 4; mt++) {
            int rb = row0 + wm * 64 + mt * 16 + quad;
            int tok0 = 0, tok1 = 0; float wt0 = 0.f, wt1 = 0.f;
            if (rb < rows)     { tok0 = g_tok[e * NTOK + rb];     wt0 = g_wt[e * NTOK + rb]; }
            if (rb + 8 < rows) { tok1 = g_tok[e * NTOK + rb + 8]; wt1 = g_wt[e * NTOK + rb + 8]; }
#pragma unroll
            for (int nt = 0; nt < 8; nt++) {
                int col = n0 + wn * 64 + nt * 8 + pair * 2;
                float bs0 = __ldg(&bias[col]), bs1 = __ldg(&bias[col + 1]);
                if (rb < rows) {
                    float* orow = out + (size_t)tok0 * DM + col;
                    atomicAdd(&orow[0], (acc[mt][nt][0] + bs0) * wt0);
                    atomicAdd(&orow[1], (acc[mt][nt][1] + bs1) * wt0);
                }
                if (rb + 8 < rows) {
                    float* orow = out + (size_t)tok1 * DM + col;
                    atomicAdd(&orow[0], (acc[mt][nt][2] + bs0) * wt1);
                    atomicAdd(&orow[1], (acc[mt][nt][3] + bs1) * wt1);
                }
            }
        }
        __syncthreads();
    }
}

// ---------------- host -------------------------------------------------------
extern "C" void kernel_launch(void* const* d_in, const int* in_sizes, int n_in,
                              void* d_out, int out_size) {
    const float* x  = (const float*)d_in[0];
    const float* gW = (const float*)d_in[1];
    const float* gb = (const float*)d_in[2];
    const float* W1 = (const float*)d_in[3];
    const float* b1 = (const float*)d_in[4];
    const float* W2 = (const float*)d_in[5];
    const float* b2 = (const float*)d_in[6];
    float* out = (float*)d_out;
    int write_topi = (out_size >= NTOK * DM + NTOK * TOPK) ? 1 : 0;

    cudaFuncSetAttribute(gemm1_mma, cudaFuncAttributeMaxDynamicSharedMemorySize, SMEM_SZ);
    cudaFuncSetAttribute(gemm2_mma, cudaFuncAttributeMaxDynamicSharedMemorySize, SMEM_SZ);

    {   // launch 0
        size_t tot4 = (size_t)NTOK * DM / 4;
        zero_kernel<<<(int)((tot4 + 255) / 256), 256>>>(out);
    }
    // launch 1
    gating_kernel<<<(NTOK * 32) / 256, 256>>>(x, gW, gb, out + (size_t)NTOK * DM,
                                              write_topi);
    // launch 2: fused weight-split (y=0,1) + gather (y=2)
    prep_kernel<<<dim3(32768, 3), 256>>>(x, W1, W2);
    // launch 3 (profiler slot): GEMM1 persistent
    gemm1_mma<<<GRID_PERSIST, THREADS, SMEM_SZ>>>(b1);
    // launch 4: GEMM2 persistent
    gemm2_mma<<<GRID_PERSIST, THREADS, SMEM_SZ>>>(b2, out);
}

// round 8
// speedup vs baseline: 1.3603x; 1.3603x over previous
#include <cuda_runtime.h>
#include <cuda_fp16.h>
#include <cstdint>
#include <math.h>

#define NTOK 16384
#define DM   1024
#define DFFN 4096
#define NE   8
#define TOPK 2
#define NSLOT (NTOK * TOPK)

#define BM 128
#define BN 128
#define BK 32
#define STAGES 4
#define THREADS 256

// ---------------- device scratch (static globals: allocation-free) ----------
__device__ int   g_cnt[NE];
__device__ int   g_tok[NE * NTOK];
__device__ float g_wt [NE * NTOK];

// padded by BM rows so tile-overhang reads stay in bounds (never written -> 0)
__device__ __align__(16) __half XGH[(size_t)(NSLOT + BM) * DM];
__device__ __align__(16) __half HH [(size_t)(NSLOT + BM) * DFFN];
__device__ __align__(16) __half W1H[(size_t)NE * DM * DFFN];
__device__ __align__(16) __half W1L[(size_t)NE * DM * DFFN];
__device__ __align__(16) __half W2H[(size_t)NE * DFFN * DM];
__device__ __align__(16) __half W2L[(size_t)NE * DFFN * DM];

// ---------------- asm helpers ----------------------------------------------
__device__ __forceinline__ void cp16(uint32_t dst, const void* src) {
    asm volatile("cp.async.cg.shared.global [%0], [%1], 16;" :: "r"(dst), "l"(src));
}
#define CP_COMMIT() asm volatile("cp.async.commit_group;" ::: "memory")
#define CP_WAIT(n)  asm volatile("cp.async.wait_group %0;" :: "n"(n) : "memory")

#define LDSM_X4(r0, r1, r2, r3, addr) \
    asm volatile("ldmatrix.sync.aligned.m8n8.x4.shared.b16 {%0,%1,%2,%3}, [%4];" \
                 : "=r"(r0), "=r"(r1), "=r"(r2), "=r"(r3) : "r"(addr))
#define LDSM_X4T(r0, r1, r2, r3, addr) \
    asm volatile("ldmatrix.sync.aligned.m8n8.x4.trans.shared.b16 {%0,%1,%2,%3}, [%4];" \
                 : "=r"(r0), "=r"(r1), "=r"(r2), "=r"(r3) : "r"(addr))

__device__ __forceinline__ void mma_f16(float* c, const uint32_t* a,
                                        uint32_t b0, uint32_t b1) {
    asm volatile(
        "mma.sync.aligned.m16n8k16.row.col.f32.f16.f16.f32 "
        "{%0,%1,%2,%3}, {%4,%5,%6,%7}, {%8,%9}, {%0,%1,%2,%3};"
        : "+f"(c[0]), "+f"(c[1]), "+f"(c[2]), "+f"(c[3])
        : "r"(a[0]), "r"(a[1]), "r"(a[2]), "r"(a[3]), "r"(b0), "r"(b1));
}

// ---------------- smem layout: per stage 24KB ------------------------------
// A 128x32 fp16 (8KB), Bh 32x128 (8KB), Bl (8KB); 4 stages = 96KB/CTA, 2 CTA/SM
#define STAGE_BYTES 24576u
#define SA(s)   ((uint32_t)(s) * STAGE_BYTES)
#define SB_H(s) ((uint32_t)(s) * STAGE_BYTES + 8192u)
#define SB_L(s) ((uint32_t)(s) * STAGE_BYTES + 16384u)
#define SMEM_SZ (STAGES * 24576)

// A: row pitch 64B (4x16B chunks), swizzle chunk ^= (row>>1)&3 (conflict-free)
__device__ __forceinline__ uint32_t a_off(int row, int ch) {
    return (uint32_t)(row * 64 + ((ch ^ ((row >> 1) & 3)) << 4));
}
// B: row pitch 256B (16x16B chunks), swizzle low3 of chunk ^= k&7
__device__ __forceinline__ uint32_t b_off(int k, int ch) {
    return (uint32_t)(k * 256 + (((ch & ~7) | ((ch ^ k) & 7)) << 4));
}

__device__ __forceinline__ float gelu_f(float v) {
    return 0.5f * v * (1.f + erff(v * 0.70710678118654752440f));
}
__device__ __forceinline__ uint32_t pack_h2(float a, float b) {
    __half x = __float2half_rn(a), y = __float2half_rn(b);
    return (uint32_t)__half_as_ushort(x) | ((uint32_t)__half_as_ushort(y) << 16);
}
__device__ __forceinline__ int expert_off(int e) {
    int off = 0;
#pragma unroll
    for (int i = 0; i < NE; i++) if (i < e) off += g_cnt[i];
    return off;
}

// ---------------- stage loader ----------------------------------------------
__device__ __forceinline__ void load_stage(
    uint32_t sb, int stage, const __half* __restrict__ A, size_t lda,
    const __half* __restrict__ Bh, const __half* __restrict__ Bl, size_t ldb,
    size_t arow0, int k0, int n0, int tid) {
#pragma unroll
    for (int i = 0; i < 2; i++) {           // A: 512 chunks
        int ca = tid + 256 * i;
        int row = ca >> 2, ch = ca & 3;
        size_t gsrc = (arow0 + row) * lda + k0 + ch * 8;
        cp16(sb + SA(stage) + a_off(row, ch), A + gsrc);
    }
#pragma unroll
    for (int i = 0; i < 2; i++) {           // B: 512 chunks per buffer
        int cb = tid + 256 * i;
        int k = cb >> 4, ch = cb & 15;
        uint32_t off = b_off(k, ch);
        size_t gsrc = (size_t)(k0 + k) * ldb + n0 + ch * 8;
        cp16(sb + SB_H(stage) + off, Bh + gsrc);
        cp16(sb + SB_L(stage) + off, Bl + gsrc);
    }
}

// ---------------- per-stage compute: 2-pass fp16 split ----------------------
// warp grid 2x4, warp tile 64x32, acc[4][4][4]
__device__ __forceinline__ void compute_stage(
    uint32_t sb, int stage, float acc[4][4][4], int wm, int wn, int lane) {
    uint32_t sa = sb + SA(stage);
    uint32_t sbH = sb + SB_H(stage), sbL = sb + SB_L(stage);
    int l15 = lane & 15, l16 = lane >> 4;
#pragma unroll
    for (int half = 0; half < 2; half++) {     // kk = half*16
        uint32_t ah[4][4];
#pragma unroll
        for (int mt = 0; mt < 4; mt++) {
            int row = wm * 64 + mt * 16 + l15;
            LDSM_X4(ah[mt][0], ah[mt][1], ah[mt][2], ah[mt][3],
                    sa + a_off(row, half * 2 + l16));
        }
        uint32_t bf[4][2];
        int kk = half * 16 + l15;
#pragma unroll
        for (int ng = 0; ng < 2; ng++) {
            uint32_t off = b_off(kk, wn * 4 + ng * 2 + l16);
            LDSM_X4T(bf[2 * ng][0], bf[2 * ng][1],
                     bf[2 * ng + 1][0], bf[2 * ng + 1][1], sbH + off);
        }
#pragma unroll
        for (int mt = 0; mt < 4; mt++)
#pragma unroll
            for (int nt = 0; nt < 4; nt++)
                mma_f16(acc[mt][nt], ah[mt], bf[nt][0], bf[nt][1]);
#pragma unroll
        for (int ng = 0; ng < 2; ng++) {
            uint32_t off = b_off(kk, wn * 4 + ng * 2 + l16);
            LDSM_X4T(bf[2 * ng][0], bf[2 * ng][1],
                     bf[2 * ng + 1][0], bf[2 * ng + 1][1], sbL + off);
        }
#pragma unroll
        for (int mt = 0; mt < 4; mt++)
#pragma unroll
            for (int nt = 0; nt < 4; nt++)
                mma_f16(acc[mt][nt], ah[mt], bf[nt][0], bf[nt][1]);
    }
}

// ---------------- launch 0: zero output + counters ---------------------------
__global__ void zero_kernel(float* __restrict__ out) {
    size_t i = (size_t)blockIdx.x * blockDim.x + threadIdx.x;
    const size_t tot4 = (size_t)NTOK * DM / 4;
    if (i < tot4) ((float4*)out)[i] = make_float4(0.f, 0.f, 0.f, 0.f);
    if (i < NE) g_cnt[i] = 0;
}

// ---------------- launch 1: gating (one warp / token) ------------------------
__global__ __launch_bounds__(256) void gating_kernel(
    const float* __restrict__ x, const float* __restrict__ gW,
    const float* __restrict__ gb, float* __restrict__ out_topi, int write_topi) {
    int warp = (int)((blockIdx.x * blockDim.x + threadIdx.x) >> 5);
    int lane = threadIdx.x & 31;
    if (warp >= NTOK) return;
    const float* xr = x + (size_t)warp * DM;
    float acc[NE];
#pragma unroll
    for (int e = 0; e < NE; e++) acc[e] = 0.f;
    for (int d = lane; d < DM; d += 32) {
        float xv = xr[d];
        const float4* w4 = (const float4*)(gW + d * NE);
        float4 wa = w4[0], wb = w4[1];
        acc[0] += xv * wa.x; acc[1] += xv * wa.y;
        acc[2] += xv * wa.z; acc[3] += xv * wa.w;
        acc[4] += xv * wb.x; acc[5] += xv * wb.y;
        acc[6] += xv * wb.z; acc[7] += xv * wb.w;
    }
#pragma unroll
    for (int e = 0; e < NE; e++)
#pragma unroll
        for (int o = 16; o > 0; o >>= 1)
            acc[e] += __shfl_xor_sync(0xffffffffu, acc[e], o);
    if (lane == 0) {
        float v0 = -1e30f, v1 = -1e30f; int i0 = 0, i1 = 0;
#pragma unroll
        for (int e = 0; e < NE; e++) {
            float l = acc[e] + gb[e];
            if (l > v0)      { v1 = v0; i1 = i0; v0 = l; i0 = e; }
            else if (l > v1) { v1 = l;  i1 = e; }
        }
        float e1 = expf(v1 - v0);
        float s  = 1.f + e1;
        float w0 = 1.f / s, w1 = e1 / s;
        int p0 = atomicAdd(&g_cnt[i0], 1);
        g_tok[i0 * NTOK + p0] = warp; g_wt[i0 * NTOK + p0] = w0;
        int p1 = atomicAdd(&g_cnt[i1], 1);
        g_tok[i1 * NTOK + p1] = warp; g_wt[i1 * NTOK + p1] = w1;
        if (write_topi) {
            out_topi[warp * 2 + 0] = (float)i0;
            out_topi[warp * 2 + 1] = (float)i1;
        }
    }
}

// ---------------- launch 2: fused prep (weight splits + routed gather) -------
__global__ __launch_bounds__(256) void prep_kernel(
    const float* __restrict__ x, const float* __restrict__ W1,
    const float* __restrict__ W2) {
    const size_t n4 = (size_t)NE * DM * DFFN / 4;
    if (blockIdx.y < 2) {                       // weight hi/lo split (fp16)
        size_t i = (size_t)blockIdx.x * blockDim.x + threadIdx.x;
        if (i >= n4) return;
        const float* src = blockIdx.y ? W2 : W1;
        __half* dh = blockIdx.y ? W2H : W1H;
        __half* dl = blockIdx.y ? W2L : W1L;
        float4 v = ((const float4*)src)[i];
        __half a0 = __float2half_rn(v.x), a1 = __float2half_rn(v.y);
        __half a2 = __float2half_rn(v.z), a3 = __float2half_rn(v.w);
        uint2 hh, ll;
        hh.x = (uint32_t)__half_as_ushort(a0) | ((uint32_t)__half_as_ushort(a1) << 16);
        hh.y = (uint32_t)__half_as_ushort(a2) | ((uint32_t)__half_as_ushort(a3) << 16);
        ll.x = pack_h2(v.x - __half2float(a0), v.y - __half2float(a1));
        ll.y = pack_h2(v.z - __half2float(a2), v.w - __half2float(a3));
        ((uint2*)dh)[i] = hh;
        ((uint2*)dl)[i] = ll;
    } else {                                    // gather routed rows -> fp16
        int e = blockIdx.x >> 12;               // 4096 x-blocks per expert
        int cnt = g_cnt[e], off = expert_off(e);
        int rbase = (blockIdx.x & 4095) * 4;
#pragma unroll
        for (int rr = 0; rr < 4; rr++) {
            int r = rbase + rr;
            if (r >= cnt) continue;
            int tok = g_tok[e * NTOK + r];
            float4 v = ((const float4*)(x + (size_t)tok * DM))[threadIdx.x];
            uint2 hh;
            hh.x = pack_h2(v.x, v.y); hh.y = pack_h2(v.z, v.w);
            ((uint2*)(XGH + (size_t)(off + r) * DM))[threadIdx.x] = hh;
        }
    }
}

// ---------------- launch 3: GEMM1  h = fp16(gelu(xg @ W1 + b1)) --------------
__global__ __launch_bounds__(THREADS, 2) void gemm1_mma(const float* __restrict__ b1) {
    extern __shared__ char smem[];
    int e = blockIdx.z;
    int rows = g_cnt[e], off = expert_off(e);
    int row0 = blockIdx.y * BM;
    if (row0 >= rows) return;
    int n0 = blockIdx.x * BN;
    uint32_t sb = (uint32_t)__cvta_generic_to_shared(smem);
    int tid = threadIdx.x, lane = tid & 31, wid = tid >> 5;
    int wm = wid & 1, wn = wid >> 1;
    const __half* Bh = W1H + (size_t)e * DM * DFFN;
    const __half* Bl = W1L + (size_t)e * DM * DFFN;
    size_t arow0 = (size_t)off + row0;

    float acc[4][4][4];
#pragma unroll
    for (int a = 0; a < 4; a++)
#pragma unroll
        for (int b = 0; b < 4; b++)
#pragma unroll
            for (int c = 0; c < 4; c++) acc[a][b][c] = 0.f;

    const int nk = DM / BK;  // 32
#pragma unroll
    for (int p = 0; p < STAGES - 1; p++) {
        load_stage(sb, p, XGH, DM, Bh, Bl, DFFN, arow0, p * BK, n0, tid);
        CP_COMMIT();
    }
    for (int t = 0; t < nk; t++) {
        CP_WAIT(STAGES - 2);
        __syncthreads();
        int nx = t + STAGES - 1;
        if (nx < nk)
            load_stage(sb, nx % STAGES, XGH, DM, Bh, Bl, DFFN,
                       arow0, nx * BK, n0, tid);
        CP_COMMIT();
        compute_stage(sb, t % STAGES, acc, wm, wn, lane);
    }

    const float* bias = b1 + (size_t)e * DFFN;
    int quad = lane >> 2, pair = lane & 3;
#pragma unroll
    for (int mt = 0; mt < 4; mt++) {
        int rb = row0 + wm * 64 + mt * 16 + quad;
#pragma unroll
        for (int nt = 0; nt < 4; nt++) {
            int col = n0 + wn * 32 + nt * 8 + pair * 2;
            float bs0 = __ldg(&bias[col]), bs1 = __ldg(&bias[col + 1]);
            if (rb < rows) {
                size_t o = (size_t)(off + rb) * DFFN + col;
                *(uint32_t*)(HH + o) =
                    pack_h2(gelu_f(acc[mt][nt][0] + bs0), gelu_f(acc[mt][nt][1] + bs1));
            }
            if (rb + 8 < rows) {
                size_t o = (size_t)(off + rb + 8) * DFFN + col;
                *(uint32_t*)(HH + o) =
                    pack_h2(gelu_f(acc[mt][nt][2] + bs0), gelu_f(acc[mt][nt][3] + bs1));
            }
        }
    }
}

// ---------------- launch 4: GEMM2  out[tok] += wt * (h @ W2 + b2) ------------
__global__ __launch_bounds__(THREADS, 2) void gemm2_mma(
    const float* __restrict__ b2, float* __restrict__ out) {
    extern __shared__ char smem[];
    int e = blockIdx.z;
    int rows = g_cnt[e], off = expert_off(e);
    int row0 = blockIdx.y * BM;
    if (row0 >= rows) return;
    int n0 = blockIdx.x * BN;
    uint32_t sb = (uint32_t)__cvta_generic_to_shared(smem);
    int tid = threadIdx.x, lane = tid & 31, wid = tid >> 5;
    int wm = wid & 1, wn = wid >> 1;
    const __half* Bh = W2H + (size_t)e * DFFN * DM;
    const __half* Bl = W2L + (size_t)e * DFFN * DM;
    size_t arow0 = (size_t)off + row0;

    float acc[4][4][4];
#pragma unroll
    for (int a = 0; a < 4; a++)
#pragma unroll
        for (int b = 0; b < 4; b++)
#pragma unroll
            for (int c = 0; c < 4; c++) acc[a][b][c] = 0.f;

    const int nk = DFFN / BK;  // 128
#pragma unroll
    for (int p = 0; p < STAGES - 1; p++) {
        load_stage(sb, p, HH, DFFN, Bh, Bl, DM, arow0, p * BK, n0, tid);
        CP_COMMIT();
    }
    for (int t = 0; t < nk; t++) {
        CP_WAIT(STAGES - 2);
        __syncthreads();
        int nx = t + STAGES - 1;
        if (nx < nk)
            load_stage(sb, nx % STAGES, HH, DFFN, Bh, Bl, DM,
                       arow0, nx * BK, n0, tid);
        CP_COMMIT();
        compute_stage(sb, t % STAGES, acc, wm, wn, lane);
    }

    const float* bias = b2 + (size_t)e * DM;
    int quad = lane >> 2, pair = lane & 3;
#pragma unroll
    for (int mt = 0; mt < 4; mt++) {
        int rb = row0 + wm * 64 + mt * 16 + quad;
        int tok0 = 0, tok1 = 0; float wt0 = 0.f, wt1 = 0.f;
        if (rb < rows)     { tok0 = g_tok[e * NTOK + rb];     wt0 = g_wt[e * NTOK + rb]; }
        if (rb + 8 < rows) { tok1 = g_tok[e * NTOK + rb + 8]; wt1 = g_wt[e * NTOK + rb + 8]; }
#pragma unroll
        for (int nt = 0; nt < 4; nt++) {
            int col = n0 + wn * 32 + nt * 8 + pair * 2;
            float bs0 = __ldg(&bias[col]), bs1 = __ldg(&bias[col + 1]);
            if (rb < rows) {
                float* orow = out + (size_t)tok0 * DM + col;
                atomicAdd(&orow[0], (acc[mt][nt][0] + bs0) * wt0);
                atomicAdd(&orow[1], (acc[mt][nt][1] + bs1) * wt0);
            }
            if (rb + 8 < rows) {
                float* orow = out + (size_t)tok1 * DM + col;
                atomicAdd(&orow[0], (acc[mt][nt][2] + bs0) * wt1);
                atomicAdd(&orow[1], (acc[mt][nt][3] + bs1) * wt1);
            }
        }
    }
}

// ---------------- host -------------------------------------------------------
extern "C" void kernel_launch(void* const* d_in, const int* in_sizes, int n_in,
                              void* d_out, int out_size) {
    const float* x  = (const float*)d_in[0];
    const float* gW = (const float*)d_in[1];
    const float* gb = (const float*)d_in[2];
    const float* W1 = (const float*)d_in[3];
    const float* b1 = (const float*)d_in[4];
    const float* W2 = (const float*)d_in[5];
    const float* b2 = (const float*)d_in[6];
    float* out = (float*)d_out;
    int write_topi = (out_size >= NTOK * DM + NTOK * TOPK) ? 1 : 0;

    cudaFuncSetAttribute(gemm1_mma, cudaFuncAttributeMaxDynamicSharedMemorySize, SMEM_SZ);
    cudaFuncSetAttribute(gemm2_mma, cudaFuncAttributeMaxDynamicSharedMemorySize, SMEM_SZ);

    {   // launch 0
        size_t tot4 = (size_t)NTOK * DM / 4;
        zero_kernel<<<(int)((tot4 + 255) / 256), 256>>>(out);
    }
    // launch 1
    gating_kernel<<<(NTOK * 32) / 256, 256>>>(x, gW, gb, out + (size_t)NTOK * DM,
                                              write_topi);
    // launch 2: fused weight-split (y=0,1) + gather (y=2)
    prep_kernel<<<dim3(32768, 3), 256>>>(x, W1, W2);
    // launch 3 (profiler slot): GEMM1, 2 CTAs/SM
    gemm1_mma<<<dim3(DFFN / BN, NTOK / BM, NE), THREADS, SMEM_SZ>>>(b1);
    // launch 4: GEMM2, 2 CTAs/SM
    gemm2_mma<<<dim3(DM / BN, NTOK / BM, NE), THREADS, SMEM_SZ>>>(b2, out);
}

// round 9
// speedup vs baseline: 2.1796x; 1.6023x over previous
#include <cuda_runtime.h>
#include <cuda_fp16.h>
#include <cstdint>
#include <math.h>

#define NTOK 16384
#define DM   1024
#define DFFN 4096
#define NE   8
#define TOPK 2
#define NSLOT (NTOK * TOPK)

#define BM 128
#define BN 128
#define BK 32
#define STAGES 4
#define THREADS 256

// ---------------- device scratch (static globals: allocation-free) ----------
__device__ int   g_cnt[NE];
__device__ int   g_tok[NE * NTOK];
__device__ float g_wt [NE * NTOK];

// padded by BM rows so tile-overhang reads stay in bounds (never written -> 0)
__device__ __align__(16) __half XGH[(size_t)(NSLOT + BM) * DM];
__device__ __align__(16) __half HH [(size_t)(NSLOT + BM) * DFFN];
__device__ __align__(16) __half W1H[(size_t)NE * DM * DFFN];
__device__ __align__(16) __half W2H[(size_t)NE * DFFN * DM];

// ---------------- asm helpers ----------------------------------------------
__device__ __forceinline__ void cp16(uint32_t dst, const void* src) {
    asm volatile("cp.async.cg.shared.global [%0], [%1], 16;" :: "r"(dst), "l"(src));
}
#define CP_COMMIT() asm volatile("cp.async.commit_group;" ::: "memory")
#define CP_WAIT(n)  asm volatile("cp.async.wait_group %0;" :: "n"(n) : "memory")

#define LDSM_X4(r0, r1, r2, r3, addr) \
    asm volatile("ldmatrix.sync.aligned.m8n8.x4.shared.b16 {%0,%1,%2,%3}, [%4];" \
                 : "=r"(r0), "=r"(r1), "=r"(r2), "=r"(r3) : "r"(addr))
#define LDSM_X4T(r0, r1, r2, r3, addr) \
    asm volatile("ldmatrix.sync.aligned.m8n8.x4.trans.shared.b16 {%0,%1,%2,%3}, [%4];" \
                 : "=r"(r0), "=r"(r1), "=r"(r2), "=r"(r3) : "r"(addr))

__device__ __forceinline__ void mma_f16(float* c, const uint32_t* a,
                                        uint32_t b0, uint32_t b1) {
    asm volatile(
        "mma.sync.aligned.m16n8k16.row.col.f32.f16.f16.f32 "
        "{%0,%1,%2,%3}, {%4,%5,%6,%7}, {%8,%9}, {%0,%1,%2,%3};"
        : "+f"(c[0]), "+f"(c[1]), "+f"(c[2]), "+f"(c[3])
        : "r"(a[0]), "r"(a[1]), "r"(a[2]), "r"(a[3]), "r"(b0), "r"(b1));
}

// ---------------- smem layout: per stage 16KB ------------------------------
// A 128x32 fp16 (8KB), B 32x128 (8KB); 4 stages = 64KB/CTA, 2 CTA/SM
#define STAGE_BYTES 16384u
#define SA(s)  ((uint32_t)(s) * STAGE_BYTES)
#define SB(s)  ((uint32_t)(s) * STAGE_BYTES + 8192u)
#define SMEM_SZ (STAGES * 16384)

// A: row pitch 64B (4x16B chunks), swizzle chunk ^= (row>>1)&3 (conflict-free)
__device__ __forceinline__ uint32_t a_off(int row, int ch) {
    return (uint32_t)(row * 64 + ((ch ^ ((row >> 1) & 3)) << 4));
}
// B: row pitch 256B (16x16B chunks), swizzle low3 of chunk ^= k&7
__device__ __forceinline__ uint32_t b_off(int k, int ch) {
    return (uint32_t)(k * 256 + (((ch & ~7) | ((ch ^ k) & 7)) << 4));
}

__device__ __forceinline__ float gelu_f(float v) {
    return 0.5f * v * (1.f + erff(v * 0.70710678118654752440f));
}
__device__ __forceinline__ uint32_t pack_h2(float a, float b) {
    __half x = __float2half_rn(a), y = __float2half_rn(b);
    return (uint32_t)__half_as_ushort(x) | ((uint32_t)__half_as_ushort(y) << 16);
}
__device__ __forceinline__ int expert_off(int e) {
    int off = 0;
#pragma unroll
    for (int i = 0; i < NE; i++) if (i < e) off += g_cnt[i];
    return off;
}

// ---------------- stage loader ----------------------------------------------
__device__ __forceinline__ void load_stage(
    uint32_t sb, int stage, const __half* __restrict__ A, size_t lda,
    const __half* __restrict__ B, size_t ldb,
    size_t arow0, int k0, int n0, int tid) {
#pragma unroll
    for (int i = 0; i < 2; i++) {           // A: 512 chunks
        int ca = tid + 256 * i;
        int row = ca >> 2, ch = ca & 3;
        size_t gsrc = (arow0 + row) * lda + k0 + ch * 8;
        cp16(sb + SA(stage) + a_off(row, ch), A + gsrc);
    }
#pragma unroll
    for (int i = 0; i < 2; i++) {           // B: 512 chunks
        int cb = tid + 256 * i;
        int k = cb >> 4, ch = cb & 15;
        size_t gsrc = (size_t)(k0 + k) * ldb + n0 + ch * 8;
        cp16(sb + SB(stage) + b_off(k, ch), B + gsrc);
    }
}

// ---------------- per-stage compute: single-pass fp16 -----------------------
// warp grid 2x4, warp tile 64x32, acc[4][4][4]
__device__ __forceinline__ void compute_stage(
    uint32_t sb, int stage, float acc[4][4][4], int wm, int wn, int lane) {
    uint32_t sa = sb + SA(stage);
    uint32_t sbB = sb + SB(stage);
    int l15 = lane & 15, l16 = lane >> 4;
#pragma unroll
    for (int half = 0; half < 2; half++) {     // kk = half*16
        uint32_t ah[4][4];
#pragma unroll
        for (int mt = 0; mt < 4; mt++) {
            int row = wm * 64 + mt * 16 + l15;
            LDSM_X4(ah[mt][0], ah[mt][1], ah[mt][2], ah[mt][3],
                    sa + a_off(row, half * 2 + l16));
        }
        uint32_t bf[4][2];
        int kk = half * 16 + l15;
#pragma unroll
        for (int ng = 0; ng < 2; ng++) {
            uint32_t off = b_off(kk, wn * 4 + ng * 2 + l16);
            LDSM_X4T(bf[2 * ng][0], bf[2 * ng][1],
                     bf[2 * ng + 1][0], bf[2 * ng + 1][1], sbB + off);
        }
#pragma unroll
        for (int mt = 0; mt < 4; mt++)
#pragma unroll
            for (int nt = 0; nt < 4; nt++)
                mma_f16(acc[mt][nt], ah[mt], bf[nt][0], bf[nt][1]);
    }
}

// ---------------- launch 0: zero output + counters ---------------------------
__global__ void zero_kernel(float* __restrict__ out) {
    size_t i = (size_t)blockIdx.x * blockDim.x + threadIdx.x;
    const size_t tot4 = (size_t)NTOK * DM / 4;
    if (i < tot4) ((float4*)out)[i] = make_float4(0.f, 0.f, 0.f, 0.f);
    if (i < NE) g_cnt[i] = 0;
}

// ---------------- launch 1: gating (one warp / token) ------------------------
__global__ __launch_bounds__(256) void gating_kernel(
    const float* __restrict__ x, const float* __restrict__ gW,
    const float* __restrict__ gb, float* __restrict__ out_topi, int write_topi) {
    int warp = (int)((blockIdx.x * blockDim.x + threadIdx.x) >> 5);
    int lane = threadIdx.x & 31;
    if (warp >= NTOK) return;
    const float* xr = x + (size_t)warp * DM;
    float acc[NE];
#pragma unroll
    for (int e = 0; e < NE; e++) acc[e] = 0.f;
    for (int d = lane; d < DM; d += 32) {
        float xv = xr[d];
        const float4* w4 = (const float4*)(gW + d * NE);
        float4 wa = w4[0], wb = w4[1];
        acc[0] += xv * wa.x; acc[1] += xv * wa.y;
        acc[2] += xv * wa.z; acc[3] += xv * wa.w;
        acc[4] += xv * wb.x; acc[5] += xv * wb.y;
        acc[6] += xv * wb.z; acc[7] += xv * wb.w;
    }
#pragma unroll
    for (int e = 0; e < NE; e++)
#pragma unroll
        for (int o = 16; o > 0; o >>= 1)
            acc[e] += __shfl_xor_sync(0xffffffffu, acc[e], o);
    if (lane == 0) {
        float v0 = -1e30f, v1 = -1e30f; int i0 = 0, i1 = 0;
#pragma unroll
        for (int e = 0; e < NE; e++) {
            float l = acc[e] + gb[e];
            if (l > v0)      { v1 = v0; i1 = i0; v0 = l; i0 = e; }
            else if (l > v1) { v1 = l;  i1 = e; }
        }
        float e1 = expf(v1 - v0);
        float s  = 1.f + e1;
        float w0 = 1.f / s, w1 = e1 / s;
        int p0 = atomicAdd(&g_cnt[i0], 1);
        g_tok[i0 * NTOK + p0] = warp; g_wt[i0 * NTOK + p0] = w0;
        int p1 = atomicAdd(&g_cnt[i1], 1);
        g_tok[i1 * NTOK + p1] = warp; g_wt[i1 * NTOK + p1] = w1;
        if (write_topi) {
            out_topi[warp * 2 + 0] = (float)i0;
            out_topi[warp * 2 + 1] = (float)i1;
        }
    }
}

// ---------------- launch 2: fused prep (weight fp16 convert + gather) --------
__global__ __launch_bounds__(256) void prep_kernel(
    const float* __restrict__ x, const float* __restrict__ W1,
    const float* __restrict__ W2) {
    const size_t n4 = (size_t)NE * DM * DFFN / 4;
    if (blockIdx.y < 2) {                       // weight fp16 convert
        size_t i = (size_t)blockIdx.x * blockDim.x + threadIdx.x;
        if (i >= n4) return;
        const float* src = blockIdx.y ? W2 : W1;
        __half* dh = blockIdx.y ? W2H : W1H;
        float4 v = ((const float4*)src)[i];
        uint2 hh;
        hh.x = pack_h2(v.x, v.y); hh.y = pack_h2(v.z, v.w);
        ((uint2*)dh)[i] = hh;
    } else {                                    // gather routed rows -> fp16
        int e = blockIdx.x >> 12;               // 4096 x-blocks per expert
        int cnt = g_cnt[e], off = expert_off(e);
        int rbase = (blockIdx.x & 4095) * 4;
#pragma unroll
        for (int rr = 0; rr < 4; rr++) {
            int r = rbase + rr;
            if (r >= cnt) continue;
            int tok = g_tok[e * NTOK + r];
            float4 v = ((const float4*)(x + (size_t)tok * DM))[threadIdx.x];
            uint2 hh;
            hh.x = pack_h2(v.x, v.y); hh.y = pack_h2(v.z, v.w);
            ((uint2*)(XGH + (size_t)(off + r) * DM))[threadIdx.x] = hh;
        }
    }
}

// ---------------- launch 3: GEMM1  h = fp16(gelu(xg @ W1 + b1)) --------------
__global__ __launch_bounds__(THREADS, 2) void gemm1_mma(const float* __restrict__ b1) {
    extern __shared__ char smem[];
    int e = blockIdx.z;
    int rows = g_cnt[e], off = expert_off(e);
    int row0 = blockIdx.y * BM;
    if (row0 >= rows) return;
    int n0 = blockIdx.x * BN;
    uint32_t sb = (uint32_t)__cvta_generic_to_shared(smem);
    int tid = threadIdx.x, lane = tid & 31, wid = tid >> 5;
    int wm = wid & 1, wn = wid >> 1;
    const __half* B = W1H + (size_t)e * DM * DFFN;
    size_t arow0 = (size_t)off + row0;

    float acc[4][4][4];
#pragma unroll
    for (int a = 0; a < 4; a++)
#pragma unroll
        for (int b = 0; b < 4; b++)
#pragma unroll
            for (int c = 0; c < 4; c++) acc[a][b][c] = 0.f;

    const int nk = DM / BK;  // 32
#pragma unroll
    for (int p = 0; p < STAGES - 1; p++) {
        load_stage(sb, p, XGH, DM, B, DFFN, arow0, p * BK, n0, tid);
        CP_COMMIT();
    }
    for (int t = 0; t < nk; t++) {
        CP_WAIT(STAGES - 2);
        __syncthreads();
        int nx = t + STAGES - 1;
        if (nx < nk)
            load_stage(sb, nx % STAGES, XGH, DM, B, DFFN,
                       arow0, nx * BK, n0, tid);
        CP_COMMIT();
        compute_stage(sb, t % STAGES, acc, wm, wn, lane);
    }

    const float* bias = b1 + (size_t)e * DFFN;
    int quad = lane >> 2, pair = lane & 3;
#pragma unroll
    for (int mt = 0; mt < 4; mt++) {
        int rb = row0 + wm * 64 + mt * 16 + quad;
#pragma unroll
        for (int nt = 0; nt < 4; nt++) {
            int col = n0 + wn * 32 + nt * 8 + pair * 2;
            float bs0 = __ldg(&bias[col]), bs1 = __ldg(&bias[col + 1]);
            if (rb < rows) {
                size_t o = (size_t)(off + rb) * DFFN + col;
                *(uint32_t*)(HH + o) =
                    pack_h2(gelu_f(acc[mt][nt][0] + bs0), gelu_f(acc[mt][nt][1] + bs1));
            }
            if (rb + 8 < rows) {
                size_t o = (size_t)(off + rb + 8) * DFFN + col;
                *(uint32_t*)(HH + o) =
                    pack_h2(gelu_f(acc[mt][nt][2] + bs0), gelu_f(acc[mt][nt][3] + bs1));
            }
        }
    }
}

// ---------------- launch 4: GEMM2  out[tok] += wt * (h @ W2 + b2) ------------
__global__ __launch_bounds__(THREADS, 2) void gemm2_mma(
    const float* __restrict__ b2, float* __restrict__ out) {
    extern __shared__ char smem[];
    int e = blockIdx.z;
    int rows = g_cnt[e], off = expert_off(e);
    int row0 = blockIdx.y * BM;
    if (row0 >= rows) return;
    int n0 = blockIdx.x * BN;
    uint32_t sb = (uint32_t)__cvta_generic_to_shared(smem);
    int tid = threadIdx.x, lane = tid & 31, wid = tid >> 5;
    int wm = wid & 1, wn = wid >> 1;
    const __half* B = W2H + (size_t)e * DFFN * DM;
    size_t arow0 = (size_t)off + row0;

    float acc[4][4][4];
#pragma unroll
    for (int a = 0; a < 4; a++)
#pragma unroll
        for (int b = 0; b < 4; b++)
#pragma unroll
            for (int c = 0; c < 4; c++) acc[a][b][c] = 0.f;

    const int nk = DFFN / BK;  // 128
#pragma unroll
    for (int p = 0; p < STAGES - 1; p++) {
        load_stage(sb, p, HH, DFFN, B, DM, arow0, p * BK, n0, tid);
        CP_COMMIT();
    }
    for (int t = 0; t < nk; t++) {
        CP_WAIT(STAGES - 2);
        __syncthreads();
        int nx = t + STAGES - 1;
        if (nx < nk)
            load_stage(sb, nx % STAGES, HH, DFFN, B, DM,
                       arow0, nx * BK, n0, tid);
        CP_COMMIT();
        compute_stage(sb, t % STAGES, acc, wm, wn, lane);
    }

    const float* bias = b2 + (size_t)e * DM;
    int quad = lane >> 2, pair = lane & 3;
#pragma unroll
    for (int mt = 0; mt < 4; mt++) {
        int rb = row0 + wm * 64 + mt * 16 + quad;
        int tok0 = 0, tok1 = 0; float wt0 = 0.f, wt1 = 0.f;
        if (rb < rows)     { tok0 = g_tok[e * NTOK + rb];     wt0 = g_wt[e * NTOK + rb]; }
        if (rb + 8 < rows) { tok1 = g_tok[e * NTOK + rb + 8]; wt1 = g_wt[e * NTOK + rb + 8]; }
#pragma unroll
        for (int nt = 0; nt < 4; nt++) {
            int col = n0 + wn * 32 + nt * 8 + pair * 2;
            float bs0 = __ldg(&bias[col]), bs1 = __ldg(&bias[col + 1]);
            if (rb < rows) {
                float* orow = out + (size_t)tok0 * DM + col;
                atomicAdd(&orow[0], (acc[mt][nt][0] + bs0) * wt0);
                atomicAdd(&orow[1], (acc[mt][nt][1] + bs1) * wt0);
            }
            if (rb + 8 < rows) {
                float* orow = out + (size_t)tok1 * DM + col;
                atomicAdd(&orow[0], (acc[mt][nt][2] + bs0) * wt1);
                atomicAdd(&orow[1], (acc[mt][nt][3] + bs1) * wt1);
            }
        }
    }
}

// ---------------- host -------------------------------------------------------
extern "C" void kernel_launch(void* const* d_in, const int* in_sizes, int n_in,
                              void* d_out, int out_size) {
    const float* x  = (const float*)d_in[0];
    const float* gW = (const float*)d_in[1];
    const float* gb = (const float*)d_in[2];
    const float* W1 = (const float*)d_in[3];
    const float* b1 = (const float*)d_in[4];
    const float* W2 = (const float*)d_in[5];
    const float* b2 = (const float*)d_in[6];
    float* out = (float*)d_out;
    int write_topi = (out_size >= NTOK * DM + NTOK * TOPK) ? 1 : 0;

    cudaFuncSetAttribute(gemm1_mma, cudaFuncAttributeMaxDynamicSharedMemorySize, SMEM_SZ);
    cudaFuncSetAttribute(gemm2_mma, cudaFuncAttributeMaxDynamicSharedMemorySize, SMEM_SZ);

    {   // launch 0
        size_t tot4 = (size_t)NTOK * DM / 4;
        zero_kernel<<<(int)((tot4 + 255) / 256), 256>>>(out);
    }
    // launch 1
    gating_kernel<<<(NTOK * 32) / 256, 256>>>(x, gW, gb, out + (size_t)NTOK * DM,
                                              write_topi);
    // launch 2: fused weight-convert (y=0,1) + gather (y=2)
    prep_kernel<<<dim3(32768, 3), 256>>>(x, W1, W2);
    // launch 3 (profiler slot): GEMM1, 2 CTAs/SM
    gemm1_mma<<<dim3(DFFN / BN, NTOK / BM, NE), THREADS, SMEM_SZ>>>(b1);
    // launch 4: GEMM2, 2 CTAs/SM
    gemm2_mma<<<dim3(DM / BN, NTOK / BM, NE), THREADS, SMEM_SZ>>>(b2, out);
}

// round 10
// speedup vs baseline: 2.2175x; 1.0174x over previous
#include <cuda_runtime.h>
#include <cuda_fp16.h>
#include <cstdint>
#include <math.h>

#define NTOK 16384
#define DM   1024
#define DFFN 4096
#define NE   8
#define TOPK 2
#define NSLOT (NTOK * TOPK)

#define BM 128
#define BN 128
#define BK 32
#define STAGES 4
#define THREADS 128

// ---------------- device scratch (static globals: allocation-free) ----------
__device__ int   g_cnt[NE];
__device__ int   g_tok[NE * NTOK];
__device__ float g_wt [NE * NTOK];

// padded by BM rows so tile-overhang reads stay in bounds (never written -> 0)
__device__ __align__(16) __half XGH[(size_t)(NSLOT + BM) * DM];
__device__ __align__(16) __half HH [(size_t)(NSLOT + BM) * DFFN];
__device__ __align__(16) __half W1H[(size_t)NE * DM * DFFN];
__device__ __align__(16) __half W2H[(size_t)NE * DFFN * DM];

// ---------------- asm helpers ----------------------------------------------
__device__ __forceinline__ void cp16(uint32_t dst, const void* src) {
    asm volatile("cp.async.cg.shared.global [%0], [%1], 16;" :: "r"(dst), "l"(src));
}
#define CP_COMMIT() asm volatile("cp.async.commit_group;" ::: "memory")
#define CP_WAIT(n)  asm volatile("cp.async.wait_group %0;" :: "n"(n) : "memory")

#define LDSM_X4(r0, r1, r2, r3, addr) \
    asm volatile("ldmatrix.sync.aligned.m8n8.x4.shared.b16 {%0,%1,%2,%3}, [%4];" \
                 : "=r"(r0), "=r"(r1), "=r"(r2), "=r"(r3) : "r"(addr))
#define LDSM_X4T(r0, r1, r2, r3, addr) \
    asm volatile("ldmatrix.sync.aligned.m8n8.x4.trans.shared.b16 {%0,%1,%2,%3}, [%4];" \
                 : "=r"(r0), "=r"(r1), "=r"(r2), "=r"(r3) : "r"(addr))

__device__ __forceinline__ void mma_f16(float* c, const uint32_t* a,
                                        uint32_t b0, uint32_t b1) {
    asm volatile(
        "mma.sync.aligned.m16n8k16.row.col.f32.f16.f16.f32 "
        "{%0,%1,%2,%3}, {%4,%5,%6,%7}, {%8,%9}, {%0,%1,%2,%3};"
        : "+f"(c[0]), "+f"(c[1]), "+f"(c[2]), "+f"(c[3])
        : "r"(a[0]), "r"(a[1]), "r"(a[2]), "r"(a[3]), "r"(b0), "r"(b1));
}

// ---------------- smem layout: per stage 16KB ------------------------------
// A 128x32 fp16 (8KB), B 32x128 (8KB); 4 stages = 64KB/CTA, 2 CTA/SM
#define STAGE_BYTES 16384u
#define SA(s)  ((uint32_t)(s) * STAGE_BYTES)
#define SB(s)  ((uint32_t)(s) * STAGE_BYTES + 8192u)
#define SMEM_SZ (STAGES * 16384)

// A: row pitch 64B (4x16B chunks), swizzle chunk ^= (row>>1)&3 (conflict-free)
__device__ __forceinline__ uint32_t a_off(int row, int ch) {
    return (uint32_t)(row * 64 + ((ch ^ ((row >> 1) & 3)) << 4));
}
// B: row pitch 256B (16x16B chunks), swizzle low3 of chunk ^= k&7
__device__ __forceinline__ uint32_t b_off(int k, int ch) {
    return (uint32_t)(k * 256 + (((ch & ~7) | ((ch ^ k) & 7)) << 4));
}

__device__ __forceinline__ float gelu_f(float v) {
    return 0.5f * v * (1.f + erff(v * 0.70710678118654752440f));
}
__device__ __forceinline__ uint32_t pack_h2(float a, float b) {
    __half x = __float2half_rn(a), y = __float2half_rn(b);
    return (uint32_t)__half_as_ushort(x) | ((uint32_t)__half_as_ushort(y) << 16);
}
__device__ __forceinline__ int expert_off(int e) {
    int off = 0;
#pragma unroll
    for (int i = 0; i < NE; i++) if (i < e) off += g_cnt[i];
    return off;
}

// ---------------- stage loader (128 threads) ---------------------------------
__device__ __forceinline__ void load_stage(
    uint32_t sb, int stage, const __half* __restrict__ A, size_t lda,
    const __half* __restrict__ B, size_t ldb,
    size_t arow0, int k0, int n0, int tid) {
#pragma unroll
    for (int i = 0; i < 4; i++) {           // A: 512 chunks
        int ca = tid + 128 * i;
        int row = ca >> 2, ch = ca & 3;
        size_t gsrc = (arow0 + row) * lda + k0 + ch * 8;
        cp16(sb + SA(stage) + a_off(row, ch), A + gsrc);
    }
#pragma unroll
    for (int i = 0; i < 4; i++) {           // B: 512 chunks
        int cb = tid + 128 * i;
        int k = cb >> 4, ch = cb & 15;
        size_t gsrc = (size_t)(k0 + k) * ldb + n0 + ch * 8;
        cp16(sb + SB(stage) + b_off(k, ch), B + gsrc);
    }
}

// ---------------- per-stage compute: single-pass fp16 -----------------------
// warp grid 2x2, warp tile 64x64, acc[4][8][4]
__device__ __forceinline__ void compute_stage(
    uint32_t sb, int stage, float acc[4][8][4], int wm, int wn, int lane) {
    uint32_t sa = sb + SA(stage);
    uint32_t sbB = sb + SB(stage);
    int l15 = lane & 15, l16 = lane >> 4;
#pragma unroll
    for (int half = 0; half < 2; half++) {     // kk = half*16
        uint32_t ah[4][4];
#pragma unroll
        for (int mt = 0; mt < 4; mt++) {
            int row = wm * 64 + mt * 16 + l15;
            LDSM_X4(ah[mt][0], ah[mt][1], ah[mt][2], ah[mt][3],
                    sa + a_off(row, half * 2 + l16));
        }
        uint32_t bf[8][2];
        int kk = half * 16 + l15;
#pragma unroll
        for (int ng = 0; ng < 4; ng++) {
            uint32_t off = b_off(kk, wn * 8 + ng * 2 + l16);
            LDSM_X4T(bf[2 * ng][0], bf[2 * ng][1],
                     bf[2 * ng + 1][0], bf[2 * ng + 1][1], sbB + off);
        }
#pragma unroll
        for (int mt = 0; mt < 4; mt++)
#pragma unroll
            for (int nt = 0; nt < 8; nt++)
                mma_f16(acc[mt][nt], ah[mt], bf[nt][0], bf[nt][1]);
    }
}

// ---------------- launch 0: zero output + counters ---------------------------
__global__ void zero_kernel(float* __restrict__ out) {
    size_t i = (size_t)blockIdx.x * blockDim.x + threadIdx.x;
    const size_t tot4 = (size_t)NTOK * DM / 4;
    if (i < tot4) ((float4*)out)[i] = make_float4(0.f, 0.f, 0.f, 0.f);
    if (i < NE) g_cnt[i] = 0;
}

// ---------------- launch 1: gating (one warp / token) ------------------------
__global__ __launch_bounds__(256) void gating_kernel(
    const float* __restrict__ x, const float* __restrict__ gW,
    const float* __restrict__ gb, float* __restrict__ out_topi, int write_topi) {
    int warp = (int)((blockIdx.x * blockDim.x + threadIdx.x) >> 5);
    int lane = threadIdx.x & 31;
    if (warp >= NTOK) return;
    const float* xr = x + (size_t)warp * DM;
    float acc[NE];
#pragma unroll
    for (int e = 0; e < NE; e++) acc[e] = 0.f;
    for (int d = lane; d < DM; d += 32) {
        float xv = xr[d];
        const float4* w4 = (const float4*)(gW + d * NE);
        float4 wa = w4[0], wb = w4[1];
        acc[0] += xv * wa.x; acc[1] += xv * wa.y;
        acc[2] += xv * wa.z; acc[3] += xv * wa.w;
        acc[4] += xv * wb.x; acc[5] += xv * wb.y;
        acc[6] += xv * wb.z; acc[7] += xv * wb.w;
    }
#pragma unroll
    for (int e = 0; e < NE; e++)
#pragma unroll
        for (int o = 16; o > 0; o >>= 1)
            acc[e] += __shfl_xor_sync(0xffffffffu, acc[e], o);
    if (lane == 0) {
        float v0 = -1e30f, v1 = -1e30f; int i0 = 0, i1 = 0;
#pragma unroll
        for (int e = 0; e < NE; e++) {
            float l = acc[e] + gb[e];
            if (l > v0)      { v1 = v0; i1 = i0; v0 = l; i0 = e; }
            else if (l > v1) { v1 = l;  i1 = e; }
        }
        float e1 = expf(v1 - v0);
        float s  = 1.f + e1;
        float w0 = 1.f / s, w1 = e1 / s;
        int p0 = atomicAdd(&g_cnt[i0], 1);
        g_tok[i0 * NTOK + p0] = warp; g_wt[i0 * NTOK + p0] = w0;
        int p1 = atomicAdd(&g_cnt[i1], 1);
        g_tok[i1 * NTOK + p1] = warp; g_wt[i1 * NTOK + p1] = w1;
        if (write_topi) {
            out_topi[warp * 2 + 0] = (float)i0;
            out_topi[warp * 2 + 1] = (float)i1;
        }
    }
}

// ---------------- launch 2: fused prep (weight fp16 convert + gather) --------
__global__ __launch_bounds__(256) void prep_kernel(
    const float* __restrict__ x, const float* __restrict__ W1,
    const float* __restrict__ W2) {
    const size_t n4 = (size_t)NE * DM * DFFN / 4;
    if (blockIdx.y < 2) {                       // weight fp16 convert
        size_t i = (size_t)blockIdx.x * blockDim.x + threadIdx.x;
        if (i >= n4) return;
        const float* src = blockIdx.y ? W2 : W1;
        __half* dh = blockIdx.y ? W2H : W1H;
        float4 v = ((const float4*)src)[i];
        uint2 hh;
        hh.x = pack_h2(v.x, v.y); hh.y = pack_h2(v.z, v.w);
        ((uint2*)dh)[i] = hh;
    } else {                                    // gather routed rows -> fp16
        int e = blockIdx.x >> 12;               // 4096 x-blocks per expert
        int cnt = g_cnt[e], off = expert_off(e);
        int rbase = (blockIdx.x & 4095) * 4;
#pragma unroll
        for (int rr = 0; rr < 4; rr++) {
            int r = rbase + rr;
            if (r >= cnt) continue;
            int tok = g_tok[e * NTOK + r];
            float4 v = ((const float4*)(x + (size_t)tok * DM))[threadIdx.x];
            uint2 hh;
            hh.x = pack_h2(v.x, v.y); hh.y = pack_h2(v.z, v.w);
            ((uint2*)(XGH + (size_t)(off + r) * DM))[threadIdx.x] = hh;
        }
    }
}

// ---------------- launch 3: GEMM1  h = fp16(gelu(xg @ W1 + b1)) --------------
__global__ __launch_bounds__(THREADS, 2) void gemm1_mma(const float* __restrict__ b1) {
    extern __shared__ char smem[];
    int e = blockIdx.z;
    int rows = g_cnt[e], off = expert_off(e);
    int row0 = blockIdx.y * BM;
    if (row0 >= rows) return;
    int n0 = blockIdx.x * BN;
    uint32_t sb = (uint32_t)__cvta_generic_to_shared(smem);
    int tid = threadIdx.x, lane = tid & 31, wid = tid >> 5;
    int wm = wid & 1, wn = wid >> 1;
    const __half* B = W1H + (size_t)e * DM * DFFN;
    size_t arow0 = (size_t)off + row0;

    float acc[4][8][4];
#pragma unroll
    for (int a = 0; a < 4; a++)
#pragma unroll
        for (int b = 0; b < 8; b++)
#pragma unroll
            for (int c = 0; c < 4; c++) acc[a][b][c] = 0.f;

    const int nk = DM / BK;  // 32
#pragma unroll
    for (int p = 0; p < STAGES - 1; p++) {
        load_stage(sb, p, XGH, DM, B, DFFN, arow0, p * BK, n0, tid);
        CP_COMMIT();
    }
    for (int t = 0; t < nk; t++) {
        CP_WAIT(STAGES - 2);
        __syncthreads();
        int nx = t + STAGES - 1;
        if (nx < nk)
            load_stage(sb, nx % STAGES, XGH, DM, B, DFFN,
                       arow0, nx * BK, n0, tid);
        CP_COMMIT();
        compute_stage(sb, t % STAGES, acc, wm, wn, lane);
    }

    const float* bias = b1 + (size_t)e * DFFN;
    int quad = lane >> 2, pair = lane & 3;
#pragma unroll
    for (int mt = 0; mt < 4; mt++) {
        int rb = row0 + wm * 64 + mt * 16 + quad;
#pragma unroll
        for (int nt = 0; nt < 8; nt++) {
            int col = n0 + wn * 64 + nt * 8 + pair * 2;
            float bs0 = __ldg(&bias[col]), bs1 = __ldg(&bias[col + 1]);
            if (rb < rows) {
                size_t o = (size_t)(off + rb) * DFFN + col;
                *(uint32_t*)(HH + o) =
                    pack_h2(gelu_f(acc[mt][nt][0] + bs0), gelu_f(acc[mt][nt][1] + bs1));
            }
            if (rb + 8 < rows) {
                size_t o = (size_t)(off + rb + 8) * DFFN + col;
                *(uint32_t*)(HH + o) =
                    pack_h2(gelu_f(acc[mt][nt][2] + bs0), gelu_f(acc[mt][nt][3] + bs1));
            }
        }
    }
}

// ---------------- launch 4: GEMM2  out[tok] += wt * (h @ W2 + b2) ------------
__global__ __launch_bounds__(THREADS, 2) void gemm2_mma(
    const float* __restrict__ b2, float* __restrict__ out) {
    extern __shared__ char smem[];
    int e = blockIdx.z;
    int rows = g_cnt[e], off = expert_off(e);
    int row0 = blockIdx.y * BM;
    if (row0 >= rows) return;
    int n0 = blockIdx.x * BN;
    uint32_t sb = (uint32_t)__cvta_generic_to_shared(smem);
    int tid = threadIdx.x, lane = tid & 31, wid = tid >> 5;
    int wm = wid & 1, wn = wid >> 1;
    const __half* B = W2H + (size_t)e * DFFN * DM;
    size_t arow0 = (size_t)off + row0;

    float acc[4][8][4];
#pragma unroll
    for (int a = 0; a < 4; a++)
#pragma unroll
        for (int b = 0; b < 8; b++)
#pragma unroll
            for (int c = 0; c < 4; c++) acc[a][b][c] = 0.f;

    const int nk = DFFN / BK;  // 128
#pragma unroll
    for (int p = 0; p < STAGES - 1; p++) {
        load_stage(sb, p, HH, DFFN, B, DM, arow0, p * BK, n0, tid);
        CP_COMMIT();
    }
    for (int t = 0; t < nk; t++) {
        CP_WAIT(STAGES - 2);
        __syncthreads();
        int nx = t + STAGES - 1;
        if (nx < nk)
            load_stage(sb, nx % STAGES, HH, DFFN, B, DM,
                       arow0, nx * BK, n0, tid);
        CP_COMMIT();
        compute_stage(sb, t % STAGES, acc, wm, wn, lane);
    }

    const float* bias = b2 + (size_t)e * DM;
    int quad = lane >> 2, pair = lane & 3;
#pragma unroll
    for (int mt = 0; mt < 4; mt++) {
        int rb = row0 + wm * 64 + mt * 16 + quad;
        int tok0 = 0, tok1 = 0; float wt0 = 0.f, wt1 = 0.f;
        if (rb < rows)     { tok0 = g_tok[e * NTOK + rb];     wt0 = g_wt[e * NTOK + rb]; }
        if (rb + 8 < rows) { tok1 = g_tok[e * NTOK + rb + 8]; wt1 = g_wt[e * NTOK + rb + 8]; }
#pragma unroll
        for (int nt = 0; nt < 8; nt++) {
            int col = n0 + wn * 64 + nt * 8 + pair * 2;
            float bs0 = __ldg(&bias[col]), bs1 = __ldg(&bias[col + 1]);
            if (rb < rows) {
                float* orow = out + (size_t)tok0 * DM + col;
                atomicAdd(&orow[0], (acc[mt][nt][0] + bs0) * wt0);
                atomicAdd(&orow[1], (acc[mt][nt][1] + bs1) * wt0);
            }
            if (rb + 8 < rows) {
                float* orow = out + (size_t)tok1 * DM + col;
                atomicAdd(&orow[0], (acc[mt][nt][2] + bs0) * wt1);
                atomicAdd(&orow[1], (acc[mt][nt][3] + bs1) * wt1);
            }
        }
    }
}

// ---------------- host -------------------------------------------------------
extern "C" void kernel_launch(void* const* d_in, const int* in_sizes, int n_in,
                              void* d_out, int out_size) {
    const float* x  = (const float*)d_in[0];
    const float* gW = (const float*)d_in[1];
    const float* gb = (const float*)d_in[2];
    const float* W1 = (const float*)d_in[3];
    const float* b1 = (const float*)d_in[4];
    const float* W2 = (const float*)d_in[5];
    const float* b2 = (const float*)d_in[6];
    float* out = (float*)d_out;
    int write_topi = (out_size >= NTOK * DM + NTOK * TOPK) ? 1 : 0;

    cudaFuncSetAttribute(gemm1_mma, cudaFuncAttributeMaxDynamicSharedMemorySize, SMEM_SZ);
    cudaFuncSetAttribute(gemm2_mma, cudaFuncAttributeMaxDynamicSharedMemorySize, SMEM_SZ);

    {   // launch 0
        size_t tot4 = (size_t)NTOK * DM / 4;
        zero_kernel<<<(int)((tot4 + 255) / 256), 256>>>(out);
    }
    // launch 1
    gating_kernel<<<(NTOK * 32) / 256, 256>>>(x, gW, gb, out + (size_t)NTOK * DM,
                                              write_topi);
    // launch 2: fused weight-convert (y=0,1) + gather (y=2)
    prep_kernel<<<dim3(32768, 3), 256>>>(x, W1, W2);
    // launch 3 (profiler slot): GEMM1, 2 CTAs/SM, warp tile 64x64
    gemm1_mma<<<dim3(DFFN / BN, NTOK / BM, NE), THREADS, SMEM_SZ>>>(b1);
    // launch 4: GEMM2
    gemm2_mma<<<dim3(DM / BN, NTOK / BM, NE), THREADS, SMEM_SZ>>>(b2, out);
}

// round 11
// speedup vs baseline: 2.2860x; 1.0309x over previous
#include <cuda_runtime.h>
#include <cuda_fp16.h>
#include <cstdint>
#include <math.h>

#define NTOK 16384
#define DM   1024
#define DFFN 4096
#define NE   8
#define TOPK 2
#define NSLOT (NTOK * TOPK)

#define BM 128
#define BN 128
#define BK 32
#define STAGES 4
#define THREADS1 256   // gemm1: 8 warps, grid 2x4, tile 64x32
#define THREADS2 128   // gemm2: 4 warps, grid 2x2, tile 64x64

// ---------------- device scratch (static globals: allocation-free) ----------
__device__ int   g_cnt[NE];
__device__ int   g_tok[NE * NTOK];
__device__ float g_wt [NE * NTOK];

// padded by BM rows so tile-overhang reads stay in bounds (never written -> 0)
__device__ __align__(16) __half XGH[(size_t)(NSLOT + BM) * DM];
__device__ __align__(16) __half HH [(size_t)(NSLOT + BM) * DFFN];
__device__ __align__(16) __half W1H[(size_t)NE * DM * DFFN];
__device__ __align__(16) __half W2H[(size_t)NE * DFFN * DM];

// ---------------- asm helpers ----------------------------------------------
__device__ __forceinline__ void cp16(uint32_t dst, const void* src) {
    asm volatile("cp.async.cg.shared.global [%0], [%1], 16;" :: "r"(dst), "l"(src));
}
#define CP_COMMIT() asm volatile("cp.async.commit_group;" ::: "memory")
#define CP_WAIT(n)  asm volatile("cp.async.wait_group %0;" :: "n"(n) : "memory")

#define LDSM_X4(r0, r1, r2, r3, addr) \
    asm volatile("ldmatrix.sync.aligned.m8n8.x4.shared.b16 {%0,%1,%2,%3}, [%4];" \
                 : "=r"(r0), "=r"(r1), "=r"(r2), "=r"(r3) : "r"(addr))
#define LDSM_X4T(r0, r1, r2, r3, addr) \
    asm volatile("ldmatrix.sync.aligned.m8n8.x4.trans.shared.b16 {%0,%1,%2,%3}, [%4];" \
                 : "=r"(r0), "=r"(r1), "=r"(r2), "=r"(r3) : "r"(addr))

__device__ __forceinline__ void mma_f16(float* c, const uint32_t* a,
                                        uint32_t b0, uint32_t b1) {
    asm volatile(
        "mma.sync.aligned.m16n8k16.row.col.f32.f16.f16.f32 "
        "{%0,%1,%2,%3}, {%4,%5,%6,%7}, {%8,%9}, {%0,%1,%2,%3};"
        : "+f"(c[0]), "+f"(c[1]), "+f"(c[2]), "+f"(c[3])
        : "r"(a[0]), "r"(a[1]), "r"(a[2]), "r"(a[3]), "r"(b0), "r"(b1));
}

// vector reduction (sm_90+): one instruction adds 2 floats to gmem
__device__ __forceinline__ void red_add_v2(float* addr, float y0, float y1) {
    asm volatile("red.global.add.v2.f32 [%0], {%1, %2};"
                 :: "l"(addr), "f"(y0), "f"(y1) : "memory");
}

// ---------------- smem layout: per stage 16KB ------------------------------
// A 128x32 fp16 (8KB), B 32x128 (8KB); 4 stages = 64KB/CTA, 2 CTA/SM
#define STAGE_BYTES 16384u
#define SA(s)  ((uint32_t)(s) * STAGE_BYTES)
#define SB(s)  ((uint32_t)(s) * STAGE_BYTES + 8192u)
#define SMEM_SZ (STAGES * 16384)

// A: row pitch 64B (4x16B chunks), swizzle chunk ^= (row>>1)&3 (conflict-free)
__device__ __forceinline__ uint32_t a_off(int row, int ch) {
    return (uint32_t)(row * 64 + ((ch ^ ((row >> 1) & 3)) << 4));
}
// B: row pitch 256B (16x16B chunks), swizzle low3 of chunk ^= k&7
__device__ __forceinline__ uint32_t b_off(int k, int ch) {
    return (uint32_t)(k * 256 + (((ch & ~7) | ((ch ^ k) & 7)) << 4));
}

__device__ __forceinline__ float gelu_f(float v) {
    return 0.5f * v * (1.f + erff(v * 0.70710678118654752440f));
}
__device__ __forceinline__ uint32_t pack_h2(float a, float b) {
    __half x = __float2half_rn(a), y = __float2half_rn(b);
    return (uint32_t)__half_as_ushort(x) | ((uint32_t)__half_as_ushort(y) << 16);
}
__device__ __forceinline__ int expert_off(int e) {
    int off = 0;
#pragma unroll
    for (int i = 0; i < NE; i++) if (i < e) off += g_cnt[i];
    return off;
}

// ---------------- stage loader, templated on thread count -------------------
template <int NT>
__device__ __forceinline__ void load_stage(
    uint32_t sb, int stage, const __half* __restrict__ A, size_t lda,
    const __half* __restrict__ B, size_t ldb,
    size_t arow0, int k0, int n0, int tid) {
#pragma unroll
    for (int i = 0; i < 512 / NT; i++) {    // A: 512 chunks
        int ca = tid + NT * i;
        int row = ca >> 2, ch = ca & 3;
        size_t gsrc = (arow0 + row) * lda + k0 + ch * 8;
        cp16(sb + SA(stage) + a_off(row, ch), A + gsrc);
    }
#pragma unroll
    for (int i = 0; i < 512 / NT; i++) {    // B: 512 chunks
        int cb = tid + NT * i;
        int k = cb >> 4, ch = cb & 15;
        size_t gsrc = (size_t)(k0 + k) * ldb + n0 + ch * 8;
        cp16(sb + SB(stage) + b_off(k, ch), B + gsrc);
    }
}

// ---------------- compute A: 8 warps, grid 2x4, warp tile 64x32 -------------
__device__ __forceinline__ void compute_stage_a(
    uint32_t sb, int stage, float acc[4][4][4], int wm, int wn, int lane) {
    uint32_t sa = sb + SA(stage);
    uint32_t sbB = sb + SB(stage);
    int l15 = lane & 15, l16 = lane >> 4;
#pragma unroll
    for (int half = 0; half < 2; half++) {
        uint32_t ah[4][4];
#pragma unroll
        for (int mt = 0; mt < 4; mt++) {
            int row = wm * 64 + mt * 16 + l15;
            LDSM_X4(ah[mt][0], ah[mt][1], ah[mt][2], ah[mt][3],
                    sa + a_off(row, half * 2 + l16));
        }
        uint32_t bf[4][2];
        int kk = half * 16 + l15;
#pragma unroll
        for (int ng = 0; ng < 2; ng++) {
            uint32_t off = b_off(kk, wn * 4 + ng * 2 + l16);
            LDSM_X4T(bf[2 * ng][0], bf[2 * ng][1],
                     bf[2 * ng + 1][0], bf[2 * ng + 1][1], sbB + off);
        }
#pragma unroll
        for (int mt = 0; mt < 4; mt++)
#pragma unroll
            for (int nt = 0; nt < 4; nt++)
                mma_f16(acc[mt][nt], ah[mt], bf[nt][0], bf[nt][1]);
    }
}

// ---------------- compute B: 4 warps, grid 2x2, warp tile 64x64 -------------
__device__ __forceinline__ void compute_stage_b(
    uint32_t sb, int stage, float acc[4][8][4], int wm, int wn, int lane) {
    uint32_t sa = sb + SA(stage);
    uint32_t sbB = sb + SB(stage);
    int l15 = lane & 15, l16 = lane >> 4;
#pragma unroll
    for (int half = 0; half < 2; half++) {
        uint32_t ah[4][4];
#pragma unroll
        for (int mt = 0; mt < 4; mt++) {
            int row = wm * 64 + mt * 16 + l15;
            LDSM_X4(ah[mt][0], ah[mt][1], ah[mt][2], ah[mt][3],
                    sa + a_off(row, half * 2 + l16));
        }
        uint32_t bf[8][2];
        int kk = half * 16 + l15;
#pragma unroll
        for (int ng = 0; ng < 4; ng++) {
            uint32_t off = b_off(kk, wn * 8 + ng * 2 + l16);
            LDSM_X4T(bf[2 * ng][0], bf[2 * ng][1],
                     bf[2 * ng + 1][0], bf[2 * ng + 1][1], sbB + off);
        }
#pragma unroll
        for (int mt = 0; mt < 4; mt++)
#pragma unroll
            for (int nt = 0; nt < 8; nt++)
                mma_f16(acc[mt][nt], ah[mt], bf[nt][0], bf[nt][1]);
    }
}

// ---------------- launch 0: zero output + counters ---------------------------
__global__ void zero_kernel(float* __restrict__ out) {
    size_t i = (size_t)blockIdx.x * blockDim.x + threadIdx.x;
    const size_t tot4 = (size_t)NTOK * DM / 4;
    if (i < tot4) ((float4*)out)[i] = make_float4(0.f, 0.f, 0.f, 0.f);
    if (i < NE) g_cnt[i] = 0;
}

// ---------------- launch 1: gating (one warp / token) ------------------------
__global__ __launch_bounds__(256) void gating_kernel(
    const float* __restrict__ x, const float* __restrict__ gW,
    const float* __restrict__ gb, float* __restrict__ out_topi, int write_topi) {
    int warp = (int)((blockIdx.x * blockDim.x + threadIdx.x) >> 5);
    int lane = threadIdx.x & 31;
    if (warp >= NTOK) return;
    const float* xr = x + (size_t)warp * DM;
    float acc[NE];
#pragma unroll
    for (int e = 0; e < NE; e++) acc[e] = 0.f;
    for (int d = lane; d < DM; d += 32) {
        float xv = xr[d];
        const float4* w4 = (const float4*)(gW + d * NE);
        float4 wa = w4[0], wb = w4[1];
        acc[0] += xv * wa.x; acc[1] += xv * wa.y;
        acc[2] += xv * wa.z; acc[3] += xv * wa.w;
        acc[4] += xv * wb.x; acc[5] += xv * wb.y;
        acc[6] += xv * wb.z; acc[7] += xv * wb.w;
    }
#pragma unroll
    for (int e = 0; e < NE; e++)
#pragma unroll
        for (int o = 16; o > 0; o >>= 1)
            acc[e] += __shfl_xor_sync(0xffffffffu, acc[e], o);
    if (lane == 0) {
        float v0 = -1e30f, v1 = -1e30f; int i0 = 0, i1 = 0;
#pragma unroll
        for (int e = 0; e < NE; e++) {
            float l = acc[e] + gb[e];
            if (l > v0)      { v1 = v0; i1 = i0; v0 = l; i0 = e; }
            else if (l > v1) { v1 = l;  i1 = e; }
        }
        float e1 = expf(v1 - v0);
        float s  = 1.f + e1;
        float w0 = 1.f / s, w1 = e1 / s;
        int p0 = atomicAdd(&g_cnt[i0], 1);
        g_tok[i0 * NTOK + p0] = warp; g_wt[i0 * NTOK + p0] = w0;
        int p1 = atomicAdd(&g_cnt[i1], 1);
        g_tok[i1 * NTOK + p1] = warp; g_wt[i1 * NTOK + p1] = w1;
        if (write_topi) {
            out_topi[warp * 2 + 0] = (float)i0;
            out_topi[warp * 2 + 1] = (float)i1;
        }
    }
}

// ---------------- launch 2: fused prep (weight fp16 convert + gather) --------
__global__ __launch_bounds__(256) void prep_kernel(
    const float* __restrict__ x, const float* __restrict__ W1,
    const float* __restrict__ W2) {
    const size_t n4 = (size_t)NE * DM * DFFN / 4;
    if (blockIdx.y < 2) {                       // weight fp16 convert
        size_t i = (size_t)blockIdx.x * blockDim.x + threadIdx.x;
        if (i >= n4) return;
        const float* src = blockIdx.y ? W2 : W1;
        __half* dh = blockIdx.y ? W2H : W1H;
        float4 v = ((const float4*)src)[i];
        uint2 hh;
        hh.x = pack_h2(v.x, v.y); hh.y = pack_h2(v.z, v.w);
        ((uint2*)dh)[i] = hh;
    } else {                                    // gather routed rows -> fp16
        int e = blockIdx.x >> 12;               // 4096 x-blocks per expert
        int cnt = g_cnt[e], off = expert_off(e);
        int rbase = (blockIdx.x & 4095) * 4;
#pragma unroll
        for (int rr = 0; rr < 4; rr++) {
            int r = rbase + rr;
            if (r >= cnt) continue;
            int tok = g_tok[e * NTOK + r];
            float4 v = ((const float4*)(x + (size_t)tok * DM))[threadIdx.x];
            uint2 hh;
            hh.x = pack_h2(v.x, v.y); hh.y = pack_h2(v.z, v.w);
            ((uint2*)(XGH + (size_t)(off + r) * DM))[threadIdx.x] = hh;
        }
    }
}

// ---------------- launch 3: GEMM1 (R9 config: 256 thr, 2 CTA/SM) -------------
__global__ __launch_bounds__(THREADS1, 2) void gemm1_mma(const float* __restrict__ b1) {
    extern __shared__ char smem[];
    int e = blockIdx.z;
    int rows = g_cnt[e], off = expert_off(e);
    int row0 = blockIdx.y * BM;
    if (row0 >= rows) return;
    int n0 = blockIdx.x * BN;
    uint32_t sb = (uint32_t)__cvta_generic_to_shared(smem);
    int tid = threadIdx.x, lane = tid & 31, wid = tid >> 5;
    int wm = wid & 1, wn = wid >> 1;
    const __half* B = W1H + (size_t)e * DM * DFFN;
    size_t arow0 = (size_t)off + row0;

    float acc[4][4][4];
#pragma unroll
    for (int a = 0; a < 4; a++)
#pragma unroll
        for (int b = 0; b < 4; b++)
#pragma unroll
            for (int c = 0; c < 4; c++) acc[a][b][c] = 0.f;

    const int nk = DM / BK;  // 32
#pragma unroll
    for (int p = 0; p < STAGES - 1; p++) {
        load_stage<THREADS1>(sb, p, XGH, DM, B, DFFN, arow0, p * BK, n0, tid);
        CP_COMMIT();
    }
    for (int t = 0; t < nk; t++) {
        CP_WAIT(STAGES - 2);
        __syncthreads();
        int nx = t + STAGES - 1;
        if (nx < nk)
            load_stage<THREADS1>(sb, nx % STAGES, XGH, DM, B, DFFN,
                                 arow0, nx * BK, n0, tid);
        CP_COMMIT();
        compute_stage_a(sb, t % STAGES, acc, wm, wn, lane);
    }

    const float* bias = b1 + (size_t)e * DFFN;
    int quad = lane >> 2, pair = lane & 3;
#pragma unroll
    for (int mt = 0; mt < 4; mt++) {
        int rb = row0 + wm * 64 + mt * 16 + quad;
#pragma unroll
        for (int nt = 0; nt < 4; nt++) {
            int col = n0 + wn * 32 + nt * 8 + pair * 2;
            float bs0 = __ldg(&bias[col]), bs1 = __ldg(&bias[col + 1]);
            if (rb < rows) {
                size_t o = (size_t)(off + rb) * DFFN + col;
                *(uint32_t*)(HH + o) =
                    pack_h2(gelu_f(acc[mt][nt][0] + bs0), gelu_f(acc[mt][nt][1] + bs1));
            }
            if (rb + 8 < rows) {
                size_t o = (size_t)(off + rb + 8) * DFFN + col;
                *(uint32_t*)(HH + o) =
                    pack_h2(gelu_f(acc[mt][nt][2] + bs0), gelu_f(acc[mt][nt][3] + bs1));
            }
        }
    }
}

// ---------------- launch 4: GEMM2 (R10 config: 128 thr, 64x64 warps) ---------
__global__ __launch_bounds__(THREADS2, 2) void gemm2_mma(
    const float* __restrict__ b2, float* __restrict__ out) {
    extern __shared__ char smem[];
    int e = blockIdx.z;
    int rows = g_cnt[e], off = expert_off(e);
    int row0 = blockIdx.y * BM;
    if (row0 >= rows) return;
    int n0 = blockIdx.x * BN;
    uint32_t sb = (uint32_t)__cvta_generic_to_shared(smem);
    int tid = threadIdx.x, lane = tid & 31, wid = tid >> 5;
    int wm = wid & 1, wn = wid >> 1;
    const __half* B = W2H + (size_t)e * DFFN * DM;
    size_t arow0 = (size_t)off + row0;

    float acc[4][8][4];
#pragma unroll
    for (int a = 0; a < 4; a++)
#pragma unroll
        for (int b = 0; b < 8; b++)
#pragma unroll
            for (int c = 0; c < 4; c++) acc[a][b][c] = 0.f;

    const int nk = DFFN / BK;  // 128
#pragma unroll
    for (int p = 0; p < STAGES - 1; p++) {
        load_stage<THREADS2>(sb, p, HH, DFFN, B, DM, arow0, p * BK, n0, tid);
        CP_COMMIT();
    }
    for (int t = 0; t < nk; t++) {
        CP_WAIT(STAGES - 2);
        __syncthreads();
        int nx = t + STAGES - 1;
        if (nx < nk)
            load_stage<THREADS2>(sb, nx % STAGES, HH, DFFN, B, DM,
                                 arow0, nx * BK, n0, tid);
        CP_COMMIT();
        compute_stage_b(sb, t % STAGES, acc, wm, wn, lane);
    }

    const float* bias = b2 + (size_t)e * DM;
    int quad = lane >> 2, pair = lane & 3;
#pragma unroll
    for (int mt = 0; mt < 4; mt++) {
        int rb = row0 + wm * 64 + mt * 16 + quad;
        int tok0 = 0, tok1 = 0; float wt0 = 0.f, wt1 = 0.f;
        if (rb < rows)     { tok0 = g_tok[e * NTOK + rb];     wt0 = g_wt[e * NTOK + rb]; }
        if (rb + 8 < rows) { tok1 = g_tok[e * NTOK + rb + 8]; wt1 = g_wt[e * NTOK + rb + 8]; }
#pragma unroll
        for (int nt = 0; nt < 8; nt++) {
            int col = n0 + wn * 64 + nt * 8 + pair * 2;
            float bs0 = __ldg(&bias[col]), bs1 = __ldg(&bias[col + 1]);
            if (rb < rows) {
                float* orow = out + (size_t)tok0 * DM + col;
                red_add_v2(orow, (acc[mt][nt][0] + bs0) * wt0,
                                 (acc[mt][nt][1] + bs1) * wt0);
            }
            if (rb + 8 < rows) {
                float* orow = out + (size_t)tok1 * DM + col;
                red_add_v2(orow, (acc[mt][nt][2] + bs0) * wt1,
                                 (acc[mt][nt][3] + bs1) * wt1);
            }
        }
    }
}

// ---------------- host -------------------------------------------------------
extern "C" void kernel_launch(void* const* d_in, const int* in_sizes, int n_in,
                              void* d_out, int out_size) {
    const float* x  = (const float*)d_in[0];
    const float* gW = (const float*)d_in[1];
    const float* gb = (const float*)d_in[2];
    const float* W1 = (const float*)d_in[3];
    const float* b1 = (const float*)d_in[4];
    const float* W2 = (const float*)d_in[5];
    const float* b2 = (const float*)d_in[6];
    float* out = (float*)d_out;
    int write_topi = (out_size >= NTOK * DM + NTOK * TOPK) ? 1 : 0;

    cudaFuncSetAttribute(gemm1_mma, cudaFuncAttributeMaxDynamicSharedMemorySize, SMEM_SZ);
    cudaFuncSetAttribute(gemm2_mma, cudaFuncAttributeMaxDynamicSharedMemorySize, SMEM_SZ);

    {   // launch 0
        size_t tot4 = (size_t)NTOK * DM / 4;
        zero_kernel<<<(int)((tot4 + 255) / 256), 256>>>(out);
    }
    // launch 1
    gating_kernel<<<(NTOK * 32) / 256, 256>>>(x, gW, gb, out + (size_t)NTOK * DM,
                                              write_topi);
    // launch 2: fused weight-convert (y=0,1) + gather (y=2)
    prep_kernel<<<dim3(32768, 3), 256>>>(x, W1, W2);
    // launch 3 (profiler slot): GEMM1, R9 geometry
    gemm1_mma<<<dim3(DFFN / BN, NTOK / BM, NE), THREADS1, SMEM_SZ>>>(b1);
    // launch 4: GEMM2, R10 geometry + v2 reductions
    gemm2_mma<<<dim3(DM / BN, NTOK / BM, NE), THREADS2, SMEM_SZ>>>(b2, out);
}